// round 2
// baseline (speedup 1.0000x reference)
#include <cuda_runtime.h>

#define NL  2048
#define NE  256
#define NH  8
#define NHW 32
#define NB  2

// Scratch (statically allocated device globals -- no runtime allocation)
__device__ float g_Q[NB*NH*NL*NHW];
__device__ float g_K[NB*NH*NL*NHW];
__device__ float g_V[NB*NH*NL*NHW];
__device__ float g_Y[NB*NL*NE];

typedef unsigned long long u64;

static __device__ __forceinline__ u64 pack2(float lo, float hi) {
    u64 r; asm("mov.b64 %0, {%1,%2};" : "=l"(r) : "f"(lo), "f"(hi)); return r;
}
static __device__ __forceinline__ void unpack2(u64 a, float& lo, float& hi) {
    asm("mov.b64 {%0,%1}, %2;" : "=f"(lo), "=f"(hi) : "l"(a));
}
// Blackwell packed fp32x2 FMA (2x scalar FFMA throughput)
static __device__ __forceinline__ void fma2(u64& acc, u64 a, u64 b) {
    asm("fma.rn.f32x2 %0, %1, %2, %3;" : "=l"(acc) : "l"(a), "l"(b), "l"(acc));
}

// ---------------------------------------------------------------------------
// GEMM (NT): C[m][n] = sum_k A[m][k] * W[n][k], K = 256.
// 64x64 CTA tile, 256 threads, 4x4 micro-tile per thread via f32x2 (m-pairs).
// EPILOGUE 0: scatter into g_Q (scaled), g_K, g_V.  EPILOGUE 1: out + bias.
// ---------------------------------------------------------------------------
template<int EPILOGUE>
__global__ __launch_bounds__(256) void gemm_nt(const float* __restrict__ A,
                                               const float* __restrict__ W,
                                               const float* __restrict__ bo,
                                               float* __restrict__ out)
{
    __shared__ __align__(16) float As[32][64];
    __shared__ __align__(16) float Bs[32][64];
    const int tid = threadIdx.x;
    const int tx = tid & 15, ty = tid >> 4;
    const int m0 = blockIdx.x * 64, n0 = blockIdx.y * 64;

    u64 acc[2][4];
    #pragma unroll
    for (int p = 0; p < 2; p++)
        #pragma unroll
        for (int j = 0; j < 4; j++) acc[p][j] = 0ULL;

    for (int kc = 0; kc < 256; kc += 32) {
        #pragma unroll
        for (int r = 0; r < 2; r++) {
            int idx = tid + r * 256;      // 0..511
            int row = idx >> 3;           // 0..63
            int c4  = (idx & 7) << 2;     // 0..28
            float4 xa = *(const float4*)&A[(size_t)(m0 + row) * 256 + kc + c4];
            As[c4+0][row] = xa.x; As[c4+1][row] = xa.y;
            As[c4+2][row] = xa.z; As[c4+3][row] = xa.w;
            float4 wa = *(const float4*)&W[(size_t)(n0 + row) * 256 + kc + c4];
            Bs[c4+0][row] = wa.x; Bs[c4+1][row] = wa.y;
            Bs[c4+2][row] = wa.z; Bs[c4+3][row] = wa.w;
        }
        __syncthreads();
        #pragma unroll
        for (int k = 0; k < 32; k++) {
            ulonglong2 a2 = *(const ulonglong2*)&As[k][ty * 4];
            float4 b4 = *(const float4*)&Bs[k][tx * 4];
            u64 bb;
            bb = pack2(b4.x, b4.x); fma2(acc[0][0], a2.x, bb); fma2(acc[1][0], a2.y, bb);
            bb = pack2(b4.y, b4.y); fma2(acc[0][1], a2.x, bb); fma2(acc[1][1], a2.y, bb);
            bb = pack2(b4.z, b4.z); fma2(acc[0][2], a2.x, bb); fma2(acc[1][2], a2.y, bb);
            bb = pack2(b4.w, b4.w); fma2(acc[0][3], a2.x, bb); fma2(acc[1][3], a2.y, bb);
        }
        __syncthreads();
    }

    #pragma unroll
    for (int p = 0; p < 2; p++) {
        #pragma unroll
        for (int j = 0; j < 4; j++) {
            float v0, v1; unpack2(acc[p][j], v0, v1);
            int n = n0 + tx * 4 + j;
            int m = m0 + ty * 4 + p * 2;   // rows m (lo) and m+1 (hi)
            if (EPILOGUE == 0) {
                // n = h*96 + part*32 + c ; part 0=q(scaled),1=k,2=v
                int h = n / 96, rem = n % 96;
                int part = rem >> 5, c = rem & 31;
                float* dst = (part == 0) ? g_Q : (part == 1 ? g_K : g_V);
                float sc = (part == 0) ? 0.17677669529663687f : 1.0f;
                int b = m >> 11, l = m & 2047;
                size_t base = (((size_t)(b * NH + h)) * NL + l) * NHW + c;
                dst[base]       = v0 * sc;
                dst[base + NHW] = v1 * sc;   // l+1, same tile => same b
            } else {
                float bias = bo[n];
                out[(size_t)m * NE + n]       = v0 + bias;
                out[(size_t)(m + 1) * NE + n] = v1 + bias;
            }
        }
    }
}

// ---------------------------------------------------------------------------
// Fused attention. CTA = (b, 16-query tile) covering ALL 8 heads (warp = head)
// so the 268MB bias stream is read fully coalesced (h innermost).
// Per 32-key tile: phase1 lane=key computes 16 scores (f32x2 over q-pairs),
// exp without max-subtraction (scores bounded, fp32 safe), p staged via smem,
// phase2 lane=dim accumulates AV (f32x2 over q-pairs). Row-sum reduced once.
// ---------------------------------------------------------------------------
__global__ __launch_bounds__(256) void attn_kernel(const float* __restrict__ bias)
{
    __shared__ __align__(16) float qT[NH][NHW][16];   // [h][d][q]
    __shared__ __align__(16) float pT[NH][NHW][20];   // [h][k][q], padded rows
    const int tid  = threadIdx.x;
    const int lane = tid & 31;
    const int h    = tid >> 5;
    const int q0   = blockIdx.x * 16;
    const int b    = blockIdx.y;
    const int bh   = b * NH + h;

    const float* Qb = g_Q + (size_t)bh * NL * NHW;
    const float* Kb = g_K + (size_t)bh * NL * NHW;
    const float* Vb = g_V + (size_t)bh * NL * NHW;

    #pragma unroll
    for (int q = 0; q < 16; q++)
        qT[h][lane][q] = Qb[(size_t)(q0 + q) * NHW + lane];
    __syncwarp();

    u64 o2[8];          // o[q][d=lane], q packed in pairs
    float lsum[16];     // per-lane partial softmax denominators
    #pragma unroll
    for (int j = 0; j < 8; j++) o2[j] = 0ULL;
    #pragma unroll
    for (int q = 0; q < 16; q++) lsum[q] = 0.f;

    const float* biasBase = bias + ((size_t)b * NL + q0) * NL * NH
                                 + (size_t)lane * NH + h;

    for (int k0 = 0; k0 < NL; k0 += 32) {
        // ---- loads for this tile (issued up front, consumed ~1000cyc later)
        float4 kv4[8];                               // K row for lane's key
        const float4* kp = (const float4*)(Kb + (size_t)(k0 + lane) * NHW);
        #pragma unroll
        for (int i = 0; i < 8; i++) kv4[i] = kp[i];

        float vv[32];                                // V column d=lane
        const float* vp = Vb + (size_t)k0 * NHW + lane;
        #pragma unroll
        for (int k = 0; k < 32; k++) vv[k] = vp[(size_t)k * NHW];

        float br[16];                                // bias[q][k=lane]
        const float* bp = biasBase + (size_t)k0 * NH;
        #pragma unroll
        for (int q = 0; q < 16; q++) br[q] = bp[(size_t)q * (NL * NH)];

        // ---- phase 1: scores s[q] for lane's key
        u64 s2[8];
        #pragma unroll
        for (int j = 0; j < 8; j++) s2[j] = 0ULL;

        const float* kr = (const float*)kv4;
        #pragma unroll
        for (int d = 0; d < 32; d++) {
            u64 kk = pack2(kr[d], kr[d]);
            const ulonglong2* qrow = (const ulonglong2*)&qT[h][d][0]; // broadcast
            ulonglong2 qa = qrow[0], qb = qrow[1], qc = qrow[2], qd = qrow[3];
            fma2(s2[0], kk, qa.x); fma2(s2[1], kk, qa.y);
            fma2(s2[2], kk, qb.x); fma2(s2[3], kk, qb.y);
            fma2(s2[4], kk, qc.x); fma2(s2[5], kk, qc.y);
            fma2(s2[6], kk, qd.x); fma2(s2[7], kk, qd.y);
        }

        // ---- exp (no max subtraction needed: |s| < ~10) + stage p
        float p[16];
        #pragma unroll
        for (int j = 0; j < 8; j++) {
            float slo, shi; unpack2(s2[j], slo, shi);
            float p0 = __expf(slo + br[2*j]);
            float p1 = __expf(shi + br[2*j+1]);
            p[2*j] = p0; p[2*j+1] = p1;
            lsum[2*j] += p0; lsum[2*j+1] += p1;
        }
        #pragma unroll
        for (int jj = 0; jj < 4; jj++)
            *(float4*)&pT[h][lane][jj*4] =
                make_float4(p[4*jj], p[4*jj+1], p[4*jj+2], p[4*jj+3]);
        __syncwarp();

        // ---- phase 2: o[q][lane] += sum_k p[q][k] * V[k][lane]
        #pragma unroll
        for (int k = 0; k < 32; k++) {
            u64 vk = pack2(vv[k], vv[k]);
            const ulonglong2* pr = (const ulonglong2*)&pT[h][k][0]; // broadcast
            ulonglong2 pa = pr[0], pb = pr[1], pc = pr[2], pd = pr[3];
            fma2(o2[0], vk, pa.x); fma2(o2[1], vk, pa.y);
            fma2(o2[2], vk, pb.x); fma2(o2[3], vk, pb.y);
            fma2(o2[4], vk, pc.x); fma2(o2[5], vk, pc.y);
            fma2(o2[6], vk, pd.x); fma2(o2[7], vk, pd.y);
        }
        __syncwarp();   // pT reused next tile
    }

    // ---- epilogue: reduce denominators across lanes, normalize, write y
    float* yout = g_Y + ((size_t)b * NL + q0) * NE + h * NHW + lane;
    #pragma unroll
    for (int j = 0; j < 8; j++) {
        float olo, ohi; unpack2(o2[j], olo, ohi);
        float l0 = lsum[2*j], l1 = lsum[2*j+1];
        #pragma unroll
        for (int off = 16; off > 0; off >>= 1) {
            l0 += __shfl_xor_sync(0xffffffffu, l0, off);
            l1 += __shfl_xor_sync(0xffffffffu, l1, off);
        }
        yout[(size_t)(2*j)   * NE] = olo / l0;
        yout[(size_t)(2*j+1) * NE] = ohi / l1;
    }
}

// ---------------------------------------------------------------------------
extern "C" void kernel_launch(void* const* d_in, const int* in_sizes, int n_in,
                              void* d_out, int out_size)
{
    const float* x    = (const float*)d_in[0];  // (2,2048,256)
    const float* bias = (const float*)d_in[1];  // (2,2048,2048,8)
    const float* Wp   = (const float*)d_in[2];  // (768,256)
    const float* Wo   = (const float*)d_in[3];  // (256,256)
    const float* bo   = (const float*)d_in[4];  // (256)
    float* out = (float*)d_out;                 // (2,2048,256)

    float* yptr;
    cudaGetSymbolAddress((void**)&yptr, g_Y);

    // 1) fused QKV projection -> head-major Q/K/V scratch (Q pre-scaled)
    gemm_nt<0><<<dim3(64, 12), 256>>>(x, Wp, nullptr, nullptr);
    // 2) fused bias-attention -> g_Y [b][l][e]
    attn_kernel<<<dim3(NL / 16, NB), 256>>>(bias);
    // 3) output projection + bias
    gemm_nt<1><<<dim3(64, 4), 256>>>(yptr, Wo, bo, out);
}

// round 3
// speedup vs baseline: 1.4106x; 1.4106x over previous
#include <cuda_runtime.h>

#define NL  2048
#define NE  256
#define NH  8
#define NHW 32
#define NB  2

// Scratch (static device globals -- no runtime allocation)
__device__ float g_Q [NB*NH*NL*NHW];   // [bh][l][d]   (pre-scaled)
__device__ float g_Kt[NB*NH*NHW*NL];   // [bh][d][l]   (transposed K)
__device__ float g_V [NB*NH*NL*NHW];   // [bh][l][d]
__device__ float g_Y [NB*NL*NE];

typedef unsigned long long u64;

static __device__ __forceinline__ u64 pack2(float lo, float hi) {
    u64 r; asm("mov.b64 %0, {%1,%2};" : "=l"(r) : "f"(lo), "f"(hi)); return r;
}
static __device__ __forceinline__ void unpack2(u64 a, float& lo, float& hi) {
    asm("mov.b64 {%0,%1}, %2;" : "=f"(lo), "=f"(hi) : "l"(a));
}
static __device__ __forceinline__ void fma2(u64& acc, u64 a, u64 b) {
    asm("fma.rn.f32x2 %0, %1, %2, %3;" : "=l"(acc) : "l"(a), "l"(b), "l"(acc));
}
static __device__ __forceinline__ void cp16(void* dst, const void* src) {
    unsigned d = (unsigned)__cvta_generic_to_shared(dst);
    asm volatile("cp.async.cg.shared.global [%0], [%1], 16;" :: "r"(d), "l"(src));
}
static __device__ __forceinline__ void cp_commit() {
    asm volatile("cp.async.commit_group;");
}
static __device__ __forceinline__ void cp_wait1() {
    asm volatile("cp.async.wait_group 1;");
}

// ---------------------------------------------------------------------------
// GEMM (NT): C[m][n] = sum_k A[m][k] * W[n][k], K=256. 128x64 tile, 256 thr,
// 8m x 4n micro-tile (m-paired f32x2).  EPI 0: scatter Q/Kt/V.  EPI 1: +bias.
// ---------------------------------------------------------------------------
template<int EPI>
__global__ __launch_bounds__(256) void gemm_nt(const float* __restrict__ A,
                                               const float* __restrict__ W,
                                               const float* __restrict__ bo,
                                               float* __restrict__ out)
{
    __shared__ __align__(16) float As[32][132];   // [k][m], padded
    __shared__ __align__(16) float Bs[32][68];    // [k][n], padded
    const int tid = threadIdx.x;
    const int tx = tid & 15, ty = tid >> 4;
    const int m0 = blockIdx.x * 128, n0 = blockIdx.y * 64;

    u64 acc[4][4];
    #pragma unroll
    for (int p = 0; p < 4; p++)
        #pragma unroll
        for (int j = 0; j < 4; j++) acc[p][j] = 0ULL;

    for (int kc = 0; kc < 256; kc += 32) {
        #pragma unroll
        for (int r = 0; r < 4; r++) {
            int idx = tid + r * 256;
            int row = idx >> 3, c4 = (idx & 7) << 2;
            float4 xa = *(const float4*)&A[(size_t)(m0 + row) * 256 + kc + c4];
            As[c4+0][row] = xa.x; As[c4+1][row] = xa.y;
            As[c4+2][row] = xa.z; As[c4+3][row] = xa.w;
        }
        #pragma unroll
        for (int r = 0; r < 2; r++) {
            int idx = tid + r * 256;
            int row = idx >> 3, c4 = (idx & 7) << 2;
            float4 wa = *(const float4*)&W[(size_t)(n0 + row) * 256 + kc + c4];
            Bs[c4+0][row] = wa.x; Bs[c4+1][row] = wa.y;
            Bs[c4+2][row] = wa.z; Bs[c4+3][row] = wa.w;
        }
        __syncthreads();
        #pragma unroll
        for (int k = 0; k < 32; k++) {
            ulonglong2 aA = *(const ulonglong2*)&As[k][ty * 8];
            ulonglong2 aB = *(const ulonglong2*)&As[k][ty * 8 + 4];
            float4 b4 = *(const float4*)&Bs[k][tx * 4];
            u64 bb;
            bb = pack2(b4.x, b4.x);
            fma2(acc[0][0], aA.x, bb); fma2(acc[1][0], aA.y, bb);
            fma2(acc[2][0], aB.x, bb); fma2(acc[3][0], aB.y, bb);
            bb = pack2(b4.y, b4.y);
            fma2(acc[0][1], aA.x, bb); fma2(acc[1][1], aA.y, bb);
            fma2(acc[2][1], aB.x, bb); fma2(acc[3][1], aB.y, bb);
            bb = pack2(b4.z, b4.z);
            fma2(acc[0][2], aA.x, bb); fma2(acc[1][2], aA.y, bb);
            fma2(acc[2][2], aB.x, bb); fma2(acc[3][2], aB.y, bb);
            bb = pack2(b4.w, b4.w);
            fma2(acc[0][3], aA.x, bb); fma2(acc[1][3], aA.y, bb);
            fma2(acc[2][3], aB.x, bb); fma2(acc[3][3], aB.y, bb);
        }
        __syncthreads();
    }

    #pragma unroll
    for (int p = 0; p < 4; p++) {
        int m = m0 + ty * 8 + 2 * p;       // rows m (lo), m+1 (hi)
        #pragma unroll
        for (int j = 0; j < 4; j++) {
            float v0, v1; unpack2(acc[p][j], v0, v1);
            int n = n0 + tx * 4 + j;
            if (EPI == 0) {
                int hh = n / 96, rem = n % 96;
                int part = rem >> 5, c = rem & 31;
                int bb_ = m >> 11, l = m & 2047;
                int bh = bb_ * NH + hh;
                if (part == 1) {
                    float* d = g_Kt + (size_t)bh * (NHW * NL) + (size_t)c * NL + l;
                    d[0] = v0; d[1] = v1;
                } else {
                    float* d = (part == 0 ? g_Q : g_V)
                             + ((size_t)bh * NL + l) * NHW + c;
                    float sc = (part == 0) ? 0.17677669529663687f : 1.0f;
                    d[0]   = v0 * sc;
                    d[NHW] = v1 * sc;
                }
            } else {
                float bias_ = bo[n];
                out[(size_t)m * NE + n]       = v0 + bias_;
                out[(size_t)(m + 1) * NE + n] = v1 + bias_;
            }
        }
    }
}

// ---------------------------------------------------------------------------
// Fused attention v2: lane = query. CTA = 8 heads (warp=head) x 32 queries.
// Q row in registers; p[k] stays in registers between QK and AV (no smem
// transpose). K^T / V / bias tiles double-buffered in smem via cp.async,
// prefetched one tile ahead. Per-lane scalar softmax denominator.
// ---------------------------------------------------------------------------
#define SM_KT 0                       // [h][s][d][k]  8*2*32*32 floats
#define SM_V  16384                   // [h][s][k][d]  8*2*32*32 floats
#define SM_BS 32768                   // [s][q][260]   2*32*260 floats
#define SMEM_FLOATS (32768 + 2*32*260)
#define SMEM_BYTES  (SMEM_FLOATS * 4)

__global__ __launch_bounds__(256, 1) void attn2(const float* __restrict__ bias)
{
    extern __shared__ float sm[];
    const int tid = threadIdx.x, lane = tid & 31, h = tid >> 5;
    const int q0 = blockIdx.x * 32, b = blockIdx.y;
    const int bh = b * NH + h;

    const float* Ktb = g_Kt + (size_t)bh * (NHW * NL);
    const float* Vb  = g_V  + (size_t)bh * (NL * NHW);

    // Q row (pre-scaled) into registers
    float qreg[32];
    {
        const float4* qp = (const float4*)(g_Q + ((size_t)bh * NL + q0 + lane) * NHW);
        #pragma unroll
        for (int i = 0; i < 8; i++) *(float4*)&qreg[i * 4] = qp[i];
    }

    u64 o2[16];
    #pragma unroll
    for (int i = 0; i < 16; i++) o2[i] = 0ULL;
    float lsum0 = 0.f, lsum1 = 0.f;

    float* ktW = sm + SM_KT + h * 2048;
    float* vW  = sm + SM_V  + h * 2048;
    const int ksub = lane & 7, kdb = lane >> 3;
    const int bq = tid >> 3, bsub = tid & 7;
    const float* bsrc0 = bias + ((size_t)(b * NL + q0 + bq)) * (NL * NH) + bsub * 4;

    auto stage = [&](int s, int k0) {
        float* kd = ktW + s * 1024;
        #pragma unroll
        for (int i = 0; i < 8; i++) {
            int d = i * 4 + kdb;
            cp16(kd + d * 32 + ksub * 4, Ktb + (size_t)d * NL + k0 + ksub * 4);
        }
        float* vd = vW + s * 1024;
        const float* vs = Vb + (size_t)k0 * NHW;
        #pragma unroll
        for (int i = 0; i < 8; i++) {
            int o = (i * 32 + lane) * 4;
            cp16(vd + o, vs + o);
        }
        float* bd = sm + SM_BS + s * (32 * 260) + bq * 260 + bsub * 4;
        const float* bsrc = bsrc0 + (size_t)k0 * NH;
        #pragma unroll
        for (int i = 0; i < 8; i++)
            cp16(bd + i * 32, bsrc + i * 32);
    };

    stage(0, 0);
    cp_commit();

    const float* bq_rd = sm + SM_BS + lane * 260 + h;

    for (int t = 0; t < 64; t++) {
        int s = t & 1;
        if (t < 63) stage(s ^ 1, (t + 1) * 32);
        cp_commit();
        cp_wait1();
        __syncthreads();

        // phase 1: scores for 32 keys (k-pairs via f32x2)
        u64 s2[16];
        #pragma unroll
        for (int i = 0; i < 16; i++) s2[i] = 0ULL;
        const float* kp = ktW + s * 1024;
        #pragma unroll
        for (int d = 0; d < 32; d++) {
            u64 qq = pack2(qreg[d], qreg[d]);
            const ulonglong2* kr = (const ulonglong2*)(kp + d * 32);
            #pragma unroll
            for (int i = 0; i < 8; i++) {
                ulonglong2 kk = kr[i];
                fma2(s2[2 * i],     kk.x, qq);
                fma2(s2[2 * i + 1], kk.y, qq);
            }
        }

        // exp (no max subtraction needed: scores bounded) + bias
        float p[32];
        const float* bp = bq_rd + s * (32 * 260);
        #pragma unroll
        for (int j = 0; j < 16; j++) {
            float s0, s1; unpack2(s2[j], s0, s1);
            float p0 = __expf(s0 + bp[(2 * j) * 8]);
            float p1 = __expf(s1 + bp[(2 * j + 1) * 8]);
            p[2 * j] = p0; p[2 * j + 1] = p1;
            lsum0 += p0; lsum1 += p1;
        }

        // phase 2: o[d] += p[k] * V[k][d]  (d-pairs via f32x2)
        const float* vp = vW + s * 1024;
        #pragma unroll
        for (int k = 0; k < 32; k++) {
            u64 pp = pack2(p[k], p[k]);
            const ulonglong2* vr = (const ulonglong2*)(vp + k * 32);
            #pragma unroll
            for (int i = 0; i < 8; i++) {
                ulonglong2 vv2 = vr[i];
                fma2(o2[2 * i],     vv2.x, pp);
                fma2(o2[2 * i + 1], vv2.y, pp);
            }
        }
        __syncthreads();
    }

    float inv = 1.0f / (lsum0 + lsum1);
    float* yo = g_Y + ((size_t)(b * NL + q0 + lane)) * NE + h * NHW;
    #pragma unroll
    for (int i = 0; i < 8; i++) {
        float a0, a1, a2, a3;
        unpack2(o2[2 * i],     a0, a1);
        unpack2(o2[2 * i + 1], a2, a3);
        ((float4*)yo)[i] = make_float4(a0 * inv, a1 * inv, a2 * inv, a3 * inv);
    }
}

// ---------------------------------------------------------------------------
extern "C" void kernel_launch(void* const* d_in, const int* in_sizes, int n_in,
                              void* d_out, int out_size)
{
    const float* x    = (const float*)d_in[0];  // (2,2048,256)
    const float* bias = (const float*)d_in[1];  // (2,2048,2048,8)
    const float* Wp   = (const float*)d_in[2];  // (768,256)
    const float* Wo   = (const float*)d_in[3];  // (256,256)
    const float* bo   = (const float*)d_in[4];  // (256)
    float* out = (float*)d_out;                 // (2,2048,256)

    float* yptr;
    cudaGetSymbolAddress((void**)&yptr, g_Y);

    cudaFuncSetAttribute(attn2, cudaFuncAttributeMaxDynamicSharedMemorySize,
                         SMEM_BYTES);

    // 1) fused QKV projection -> Q (scaled), K^T, V scratch
    gemm_nt<0><<<dim3(32, 12), 256>>>(x, Wp, nullptr, nullptr);
    // 2) fused bias-attention -> g_Y
    attn2<<<dim3(NL / 32, NB), 256, SMEM_BYTES>>>(bias);
    // 3) output projection + bias
    gemm_nt<1><<<dim3(32, 4), 256>>>(yptr, Wo, bo, out);
}